// round 1
// baseline (speedup 1.0000x reference)
#include <cuda_runtime.h>

#define DD 128
#define GG 384
#define BV 256
#define MM 32
#define LL 24
#define NOUT 193
#define NSEQ 9

// ---------------- scratch (static device globals; no allocation) -------------
__device__ float g_e3[3 * BV * DD];            // cond/proc/drug visit embeddings
__device__ float g_mon[2 * BV * MM * DD];      // lab / inj monitor embeddings
__device__ float g_xg34[2 * BV * MM * GG];     // monitor input-gates, keys 3,4
__device__ float g_xg012[3 * BV * GG];         // monitor input-gates, keys 0-2 (t-invariant)
__device__ float g_h5[5 * BV * DD];            // monitor final hidden
__device__ float g_vxg[7 * 16 * 16 * GG];      // visit input-gates
__device__ float g_hv[7 * 16 * DD];            // visit final hidden
__device__ float g_wT[24 * DD * GG];           // transposed weights [d][g]

#define WIH_M 0
#define WHH_M (5 * DD * GG)
#define WIH_V (10 * DD * GG)
#define WHH_V (17 * DD * GG)

__device__ __forceinline__ float sigf(float x) { return 1.0f / (1.0f + __expf(-x)); }

// ---------------- K0: transpose all GRU weights to [d][g] --------------------
__global__ void k_transpose(const float* mih, const float* mhh,
                            const float* vih, const float* vhh) {
    int y = blockIdx.y;      // 0..23: which (tensor,key)
    int g = blockIdx.x;      // 0..383
    int d = threadIdx.x;     // 0..127
    const float* src; int k;
    if (y < 5)       { src = mih; k = y; }
    else if (y < 10) { src = mhh; k = y - 5; }
    else if (y < 17) { src = vih; k = y - 10; }
    else             { src = vhh; k = y - 17; }
    g_wT[y * (DD * GG) + d * GG + g] = src[(k * GG + g) * DD + d];
}

// ---------------- K1: visit-event embedding sums ------------------------------
__global__ void k_embed_visit(const int* tc, const int* tp, const int* td,
                              const float* ec, const float* ep, const float* ed) {
    int n = blockIdx.x, key = blockIdx.y, d = threadIdx.x;
    const int* tok = (key == 0) ? tc : (key == 1) ? tp : td;
    const float* emb = (key == 0) ? ec : (key == 1) ? ep : ed;
    float acc = 0.f;
#pragma unroll
    for (int l = 0; l < LL; l++) acc += emb[tok[n * LL + l] * DD + d];
    g_e3[(key * BV + n) * DD + d] = acc;
}

// ---------------- K2: monitor-event pair embedding sums (float4) -------------
__global__ void k_embed_mon(const int* tli, const int* tlv,
                            const int* tii, const int* tiv,
                            const float* eli, const float* elv,
                            const float* eii, const float* eiv) {
    int pair = blockIdx.y;
    int r = blockIdx.x * 4 + (threadIdx.x >> 5);   // monitor row 0..8191
    int lane = threadIdx.x & 31;
    const int* ti = pair ? tii : tli;
    const int* tv = pair ? tiv : tlv;
    const float4* ei = (const float4*)(pair ? eii : eli);
    const float4* ev = (const float4*)(pair ? eiv : elv);
    float4 acc = make_float4(0.f, 0.f, 0.f, 0.f);
#pragma unroll
    for (int l = 0; l < LL; l++) {
        int a = ti[r * LL + l];
        int b = tv[r * LL + l];
        float4 x = ei[a * 32 + lane];
        float4 y = ev[b * 32 + lane];
        acc.x += x.x * y.x; acc.y += x.y * y.y;
        acc.z += x.z * y.z; acc.w += x.w * y.w;
    }
    ((float4*)g_mon)[(pair * 8192 + r) * 32 + lane] = acc;
}

// ---------------- K3a: monitor input-gates for keys 3,4 ----------------------
__global__ void __launch_bounds__(384) k_xg34(const float* bih) {
    __shared__ float sx[DD * 36];   // x transposed [d][t], pad 4 (16B-aligned rows)
    int pair = blockIdx.y, n = blockIdx.x, key = 3 + pair;
    int g = threadIdx.x;
    for (int i = g; i < MM * DD; i += GG) {
        int t = i / DD, d = i % DD;
        sx[d * 36 + t] = g_mon[((pair * BV + n) * MM + t) * DD + d];
    }
    __syncthreads();
    float b = bih[key * GG + g];
    float acc[MM];
#pragma unroll
    for (int t = 0; t < MM; t++) acc[t] = b;
    const float* w = &g_wT[WIH_M + key * (DD * GG) + g];
    for (int d = 0; d < DD; d++) {
        float wv = w[d * GG];
        const float4* x4 = (const float4*)&sx[d * 36];
#pragma unroll
        for (int q = 0; q < 8; q++) {
            float4 x = x4[q];
            acc[q * 4 + 0] += wv * x.x; acc[q * 4 + 1] += wv * x.y;
            acc[q * 4 + 2] += wv * x.z; acc[q * 4 + 3] += wv * x.w;
        }
    }
    float* out = &g_xg34[((pair * BV + n) * MM) * GG + g];
#pragma unroll
    for (int t = 0; t < MM; t++) out[t * GG] = acc[t];
}

// ---------------- K3b: monitor input-gates for keys 0-2 (t-invariant) --------
__global__ void k_xg012(const float* bih) {
    __shared__ float sx[DD];
    int key = blockIdx.y, n = blockIdx.x, g = threadIdx.x;
    if (g < DD) sx[g] = g_e3[(key * BV + n) * DD + g];
    __syncthreads();
    float acc = bih[key * GG + g];
    const float* w = &g_wT[WIH_M + key * (DD * GG) + g];
#pragma unroll 4
    for (int d = 0; d < DD; d++) acc += w[d * GG] * sx[d];
    g_xg012[(key * BV + n) * GG + g] = acc;
}

// ---------------- K4: monitor GRU recurrence ----------------------------------
// grid (29, 5), block 384, dyn smem = (DD*GG + NSEQ*DD + NSEQ*GG)*4 = 215040 B
__global__ void __launch_bounds__(384) k_mon_gru(const float* bhh) {
    extern __shared__ float sm[];
    float* s_w = sm;                       // [d][g] 49152
    float* s_h = sm + DD * GG;             // [s][d] 1152
    float* s_gh = s_h + NSEQ * DD;         // [s][g] 3456
    int key = blockIdx.y, grp = blockIdx.x, g = threadIdx.x;
    int n0 = grp * NSEQ;
    int ns = min(NSEQ, BV - n0);
    for (int i = g; i < DD * GG; i += GG) s_w[i] = g_wT[WHH_M + key * (DD * GG) + i];
    for (int i = g; i < NSEQ * DD; i += GG) s_h[i] = 0.f;
    __syncthreads();
    float bb = bhh[key * GG + g];
    for (int t = 0; t < MM; t++) {
        float acc[NSEQ];
#pragma unroll
        for (int s = 0; s < NSEQ; s++) acc[s] = bb;
        for (int d = 0; d < DD; d++) {
            float w = s_w[d * GG + g];
#pragma unroll
            for (int s = 0; s < NSEQ; s++) acc[s] += w * s_h[s * DD + d];
        }
#pragma unroll
        for (int s = 0; s < NSEQ; s++) s_gh[s * GG + g] = acc[s];
        __syncthreads();
        int ss = g >> 7, d = g & 127;
        for (int sb = 0; sb < NSEQ; sb += 3) {
            int s = sb + ss;
            if (s < ns) {
                int n = n0 + s;
                float xr, xz, xn;
                if (key < 3) {
                    const float* xg = &g_xg012[(key * BV + n) * GG];
                    xr = xg[d]; xz = xg[DD + d]; xn = xg[2 * DD + d];
                } else {
                    const float* xg = &g_xg34[(((key - 3) * BV + n) * MM + t) * GG];
                    xr = xg[d]; xz = xg[DD + d]; xn = xg[2 * DD + d];
                }
                float ghr = s_gh[s * GG + d];
                float ghz = s_gh[s * GG + DD + d];
                float ghn = s_gh[s * GG + 2 * DD + d];
                float h = s_h[s * DD + d];
                float r = sigf(xr + ghr);
                float z = sigf(xz + ghz);
                float nn = tanhf(xn + r * ghn);
                s_h[s * DD + d] = (1.f - z) * nn + z * h;
            }
        }
        __syncthreads();
    }
    for (int i = g; i < ns * DD; i += GG) g_h5[(key * BV + n0) * DD + i] = s_h[i];
}

// ---------------- K5: visit input-gates ---------------------------------------
__global__ void __launch_bounds__(384) k_vxg(const float* weight, const float* age,
                                             const float* info_w, const float* info_b,
                                             const float* bih) {
    __shared__ float sx[16 * DD];
    int key = blockIdx.y, b = blockIdx.x, g = threadIdx.x;
    for (int i = g; i < 16 * DD; i += GG) {
        int v = i / DD, d = i % DD;
        float x;
        if (key < 5)      x = g_h5[(key * BV + b * 16 + v) * DD + d];
        else if (key == 5) x = weight[b * 16 + v] * info_w[d] + info_b[d];
        else               x = age[b * 16 + v] * info_w[DD + d] + info_b[DD + d];
        sx[i] = x;
    }
    __syncthreads();
    float bb = bih[key * GG + g];
    float acc[16];
#pragma unroll
    for (int v = 0; v < 16; v++) acc[v] = bb;
    const float* w = &g_wT[WIH_V + key * (DD * GG) + g];
    for (int d = 0; d < DD; d++) {
        float wv = w[d * GG];
#pragma unroll
        for (int v = 0; v < 16; v++) acc[v] += wv * sx[v * DD + d];
    }
    float* out = &g_vxg[((key * 16 + b) * 16) * GG + g];
#pragma unroll
    for (int v = 0; v < 16; v++) out[v * GG] = acc[v];
}

// ---------------- K6: visit GRU recurrence -------------------------------------
// grid (16, 7), block 384, dyn smem = (DD*GG + DD + GG)*4 = 198656 B
__global__ void __launch_bounds__(384) k_vis_gru(const float* bhh) {
    extern __shared__ float sm[];
    float* s_w = sm;
    float* s_h = sm + DD * GG;
    float* s_gh = s_h + DD;
    int key = blockIdx.y, b = blockIdx.x, g = threadIdx.x;
    for (int i = g; i < DD * GG; i += GG) s_w[i] = g_wT[WHH_V + key * (DD * GG) + i];
    if (g < DD) s_h[g] = 0.f;
    __syncthreads();
    float bb = bhh[key * GG + g];
    for (int t = 0; t < 16; t++) {
        float acc = bb;
#pragma unroll 4
        for (int d = 0; d < DD; d++) acc += s_w[d * GG + g] * s_h[d];
        s_gh[g] = acc;
        __syncthreads();
        if (g < DD) {
            const float* xg = &g_vxg[((key * 16 + b) * 16 + t) * GG];
            float r = sigf(xg[g] + s_gh[g]);
            float z = sigf(xg[DD + g] + s_gh[DD + g]);
            float nn = tanhf(xg[2 * DD + g] + r * s_gh[2 * DD + g]);
            s_h[g] = (1.f - z) * nn + z * s_h[g];
        }
        __syncthreads();
    }
    if (g < DD) g_hv[(key * 16 + b) * DD + g] = s_h[g];
}

// ---------------- K7: ReLU + final FC ------------------------------------------
__global__ void k_fc(const float* fcw, const float* fcb, float* out) {
    __shared__ float pe[7 * DD];
    int b = blockIdx.x, o = threadIdx.x;
    for (int i = o; i < 7 * DD; i += 256) {
        int k = i / DD, d = i % DD;
        pe[i] = fmaxf(g_hv[(k * 16 + b) * DD + d], 0.f);
    }
    __syncthreads();
    if (o < NOUT) {
        float acc = fcb[o];
        for (int j = 0; j < 7 * DD; j++) acc += pe[j] * fcw[j * NOUT + o];
        out[b * NOUT + o] = acc;
    }
}

// ---------------- launch ---------------------------------------------------------
extern "C" void kernel_launch(void* const* d_in, const int* in_sizes, int n_in,
                              void* d_out, int out_size) {
    const int* tok_cond      = (const int*)d_in[0];
    const int* tok_proc      = (const int*)d_in[1];
    const int* tok_drug      = (const int*)d_in[2];
    const int* tok_lab_item  = (const int*)d_in[3];
    const int* tok_lab_value = (const int*)d_in[4];
    const int* tok_inj_item  = (const int*)d_in[5];
    const int* tok_inj_value = (const int*)d_in[6];
    const float* weight      = (const float*)d_in[7];
    const float* age         = (const float*)d_in[8];
    const float* emb_cond    = (const float*)d_in[9];
    const float* emb_proc    = (const float*)d_in[10];
    const float* emb_drug    = (const float*)d_in[11];
    const float* emb_li      = (const float*)d_in[12];
    const float* emb_lv      = (const float*)d_in[13];
    const float* emb_ii      = (const float*)d_in[14];
    const float* emb_iv      = (const float*)d_in[15];
    const float* mgru_wih    = (const float*)d_in[16];
    const float* mgru_whh    = (const float*)d_in[17];
    const float* mgru_bih    = (const float*)d_in[18];
    const float* mgru_bhh    = (const float*)d_in[19];
    const float* vgru_wih    = (const float*)d_in[20];
    const float* vgru_whh    = (const float*)d_in[21];
    const float* vgru_bih    = (const float*)d_in[22];
    const float* vgru_bhh    = (const float*)d_in[23];
    const float* info_w      = (const float*)d_in[24];
    const float* info_b      = (const float*)d_in[25];
    const float* fc_w        = (const float*)d_in[26];
    const float* fc_b        = (const float*)d_in[27];
    float* out = (float*)d_out;

    cudaFuncSetAttribute(k_mon_gru, cudaFuncAttributeMaxDynamicSharedMemorySize, 215040);
    cudaFuncSetAttribute(k_vis_gru, cudaFuncAttributeMaxDynamicSharedMemorySize, 198656);

    k_transpose<<<dim3(384, 24), 128>>>(mgru_wih, mgru_whh, vgru_wih, vgru_whh);
    k_embed_visit<<<dim3(256, 3), 128>>>(tok_cond, tok_proc, tok_drug,
                                         emb_cond, emb_proc, emb_drug);
    k_embed_mon<<<dim3(2048, 2), 128>>>(tok_lab_item, tok_lab_value,
                                        tok_inj_item, tok_inj_value,
                                        emb_li, emb_lv, emb_ii, emb_iv);
    k_xg34<<<dim3(256, 2), 384>>>(mgru_bih);
    k_xg012<<<dim3(256, 3), 384>>>(mgru_bih);
    k_mon_gru<<<dim3(29, 5), 384, 215040>>>(mgru_bhh);
    k_vxg<<<dim3(16, 7), 384>>>(weight, age, info_w, info_b, vgru_bih);
    k_vis_gru<<<dim3(16, 7), 384, 198656>>>(vgru_bhh);
    k_fc<<<16, 256>>>(fc_w, fc_b, out);
}

// round 2
// speedup vs baseline: 1.0138x; 1.0138x over previous
#include <cuda_runtime.h>

#define DD 128
#define GG 384
#define BV 256
#define MM 32
#define LL 24
#define NOUT 193
#define NSEQ 9

// ---------------- scratch (static device globals; no allocation) -------------
__device__ float g_e3[3 * BV * DD];            // cond/proc/drug visit embeddings
__device__ float g_mon[2 * BV * MM * DD];      // lab / inj monitor embeddings
__device__ float g_xg34[2 * BV * MM * GG];     // monitor input-gates, keys 3,4
__device__ float g_xg012[3 * BV * GG];         // monitor input-gates, keys 0-2 (t-invariant)
__device__ float g_h5[5 * BV * DD];            // monitor final hidden
__device__ float g_vxg[7 * 16 * 16 * GG];      // visit input-gates
__device__ float g_hv[7 * 16 * DD];            // visit final hidden
__device__ float g_wT[24 * DD * GG];           // transposed weights [d][g]

#define WIH_M 0
#define WHH_M (5 * DD * GG)
#define WIH_V (10 * DD * GG)
#define WHH_V (17 * DD * GG)

__device__ __forceinline__ float sigf(float x) { return 1.0f / (1.0f + __expf(-x)); }

// ---------------- K0: transpose all GRU weights to [d][g] --------------------
__global__ void k_transpose(const float* mih, const float* mhh,
                            const float* vih, const float* vhh) {
    int y = blockIdx.y;      // 0..23: which (tensor,key)
    int g = blockIdx.x;      // 0..383
    int d = threadIdx.x;     // 0..127
    const float* src; int k;
    if (y < 5)       { src = mih; k = y; }
    else if (y < 10) { src = mhh; k = y - 5; }
    else if (y < 17) { src = vih; k = y - 10; }
    else             { src = vhh; k = y - 17; }
    g_wT[y * (DD * GG) + d * GG + g] = src[(k * GG + g) * DD + d];
}

// ---------------- K1: visit-event embedding sums ------------------------------
__global__ void k_embed_visit(const int* tc, const int* tp, const int* td,
                              const float* ec, const float* ep, const float* ed) {
    int n = blockIdx.x, key = blockIdx.y, d = threadIdx.x;
    const int* tok = (key == 0) ? tc : (key == 1) ? tp : td;
    const float* emb = (key == 0) ? ec : (key == 1) ? ep : ed;
    float acc = 0.f;
#pragma unroll
    for (int l = 0; l < LL; l++) acc += emb[tok[n * LL + l] * DD + d];
    g_e3[(key * BV + n) * DD + d] = acc;
}

// ---------------- K2: monitor-event pair embedding sums (float4) -------------
__global__ void k_embed_mon(const int* tli, const int* tlv,
                            const int* tii, const int* tiv,
                            const float* eli, const float* elv,
                            const float* eii, const float* eiv) {
    int pair = blockIdx.y;
    int r = blockIdx.x * 4 + (threadIdx.x >> 5);   // monitor row 0..8191
    int lane = threadIdx.x & 31;
    const int* ti = pair ? tii : tli;
    const int* tv = pair ? tiv : tlv;
    const float4* ei = (const float4*)(pair ? eii : eli);
    const float4* ev = (const float4*)(pair ? eiv : elv);
    float4 acc = make_float4(0.f, 0.f, 0.f, 0.f);
#pragma unroll
    for (int l = 0; l < LL; l++) {
        int a = ti[r * LL + l];
        int b = tv[r * LL + l];
        float4 x = ei[a * 32 + lane];
        float4 y = ev[b * 32 + lane];
        acc.x += x.x * y.x; acc.y += x.y * y.y;
        acc.z += x.z * y.z; acc.w += x.w * y.w;
    }
    ((float4*)g_mon)[(pair * 8192 + r) * 32 + lane] = acc;
}

// ---------------- K3a: monitor input-gates for keys 3,4 ----------------------
__global__ void __launch_bounds__(384) k_xg34(const float* bih) {
    __shared__ float sx[DD * 36];   // x transposed [d][t], pad 4 (16B-aligned rows)
    int pair = blockIdx.y, n = blockIdx.x, key = 3 + pair;
    int g = threadIdx.x;
    for (int i = g; i < MM * DD; i += GG) {
        int t = i / DD, d = i % DD;
        sx[d * 36 + t] = g_mon[((pair * BV + n) * MM + t) * DD + d];
    }
    __syncthreads();
    float b = bih[key * GG + g];
    float acc[MM];
#pragma unroll
    for (int t = 0; t < MM; t++) acc[t] = b;
    const float* w = &g_wT[WIH_M + key * (DD * GG) + g];
    for (int d = 0; d < DD; d++) {
        float wv = w[d * GG];
        const float4* x4 = (const float4*)&sx[d * 36];
#pragma unroll
        for (int q = 0; q < 8; q++) {
            float4 x = x4[q];
            acc[q * 4 + 0] += wv * x.x; acc[q * 4 + 1] += wv * x.y;
            acc[q * 4 + 2] += wv * x.z; acc[q * 4 + 3] += wv * x.w;
        }
    }
    float* out = &g_xg34[((pair * BV + n) * MM) * GG + g];
#pragma unroll
    for (int t = 0; t < MM; t++) out[t * GG] = acc[t];
}

// ---------------- K3b: monitor input-gates for keys 0-2 (t-invariant) --------
__global__ void k_xg012(const float* bih) {
    __shared__ float sx[DD];
    int key = blockIdx.y, n = blockIdx.x, g = threadIdx.x;
    if (g < DD) sx[g] = g_e3[(key * BV + n) * DD + g];
    __syncthreads();
    float acc = bih[key * GG + g];
    const float* w = &g_wT[WIH_M + key * (DD * GG) + g];
#pragma unroll 4
    for (int d = 0; d < DD; d++) acc += w[d * GG] * sx[d];
    g_xg012[(key * BV + n) * GG + g] = acc;
}

// ---------------- K4: monitor GRU recurrence ----------------------------------
// grid (29, 5), block 384, dyn smem = (DD*GG + NSEQ*DD + NSEQ*GG)*4 = 215040 B
__global__ void __launch_bounds__(384) k_mon_gru(const float* bhh) {
    extern __shared__ float sm[];
    float* s_w = sm;                       // [d][g] 49152
    float* s_h = sm + DD * GG;             // [s][d] 1152
    float* s_gh = s_h + NSEQ * DD;         // [s][g] 3456
    int key = blockIdx.y, grp = blockIdx.x, g = threadIdx.x;
    int n0 = grp * NSEQ;
    int ns = min(NSEQ, BV - n0);
    for (int i = g; i < DD * GG; i += GG) s_w[i] = g_wT[WHH_M + key * (DD * GG) + i];
    for (int i = g; i < NSEQ * DD; i += GG) s_h[i] = 0.f;
    __syncthreads();
    float bb = bhh[key * GG + g];
    for (int t = 0; t < MM; t++) {
        float acc[NSEQ];
#pragma unroll
        for (int s = 0; s < NSEQ; s++) acc[s] = bb;
        for (int d = 0; d < DD; d++) {
            float w = s_w[d * GG + g];
#pragma unroll
            for (int s = 0; s < NSEQ; s++) acc[s] += w * s_h[s * DD + d];
        }
#pragma unroll
        for (int s = 0; s < NSEQ; s++) s_gh[s * GG + g] = acc[s];
        __syncthreads();
        int ss = g >> 7, d = g & 127;
        for (int sb = 0; sb < NSEQ; sb += 3) {
            int s = sb + ss;
            if (s < ns) {
                int n = n0 + s;
                float xr, xz, xn;
                if (key < 3) {
                    const float* xg = &g_xg012[(key * BV + n) * GG];
                    xr = xg[d]; xz = xg[DD + d]; xn = xg[2 * DD + d];
                } else {
                    const float* xg = &g_xg34[(((key - 3) * BV + n) * MM + t) * GG];
                    xr = xg[d]; xz = xg[DD + d]; xn = xg[2 * DD + d];
                }
                float ghr = s_gh[s * GG + d];
                float ghz = s_gh[s * GG + DD + d];
                float ghn = s_gh[s * GG + 2 * DD + d];
                float h = s_h[s * DD + d];
                float r = sigf(xr + ghr);
                float z = sigf(xz + ghz);
                float nn = tanhf(xn + r * ghn);
                s_h[s * DD + d] = (1.f - z) * nn + z * h;
            }
        }
        __syncthreads();
    }
    for (int i = g; i < ns * DD; i += GG) g_h5[(key * BV + n0) * DD + i] = s_h[i];
}

// ---------------- K5: visit input-gates ---------------------------------------
__global__ void __launch_bounds__(384) k_vxg(const float* weight, const float* age,
                                             const float* info_w, const float* info_b,
                                             const float* bih) {
    __shared__ float sx[16 * DD];
    int key = blockIdx.y, b = blockIdx.x, g = threadIdx.x;
    for (int i = g; i < 16 * DD; i += GG) {
        int v = i / DD, d = i % DD;
        float x;
        if (key < 5)      x = g_h5[(key * BV + b * 16 + v) * DD + d];
        else if (key == 5) x = weight[b * 16 + v] * info_w[d] + info_b[d];
        else               x = age[b * 16 + v] * info_w[DD + d] + info_b[DD + d];
        sx[i] = x;
    }
    __syncthreads();
    float bb = bih[key * GG + g];
    float acc[16];
#pragma unroll
    for (int v = 0; v < 16; v++) acc[v] = bb;
    const float* w = &g_wT[WIH_V + key * (DD * GG) + g];
    for (int d = 0; d < DD; d++) {
        float wv = w[d * GG];
#pragma unroll
        for (int v = 0; v < 16; v++) acc[v] += wv * sx[v * DD + d];
    }
    float* out = &g_vxg[((key * 16 + b) * 16) * GG + g];
#pragma unroll
    for (int v = 0; v < 16; v++) out[v * GG] = acc[v];
}

// ---------------- K6: visit GRU recurrence -------------------------------------
// grid (16, 7), block 384, dyn smem = (DD*GG + DD + GG)*4 = 198656 B
__global__ void __launch_bounds__(384) k_vis_gru(const float* bhh) {
    extern __shared__ float sm[];
    float* s_w = sm;
    float* s_h = sm + DD * GG;
    float* s_gh = s_h + DD;
    int key = blockIdx.y, b = blockIdx.x, g = threadIdx.x;
    for (int i = g; i < DD * GG; i += GG) s_w[i] = g_wT[WHH_V + key * (DD * GG) + i];
    if (g < DD) s_h[g] = 0.f;
    __syncthreads();
    float bb = bhh[key * GG + g];
    for (int t = 0; t < 16; t++) {
        float acc = bb;
#pragma unroll 4
        for (int d = 0; d < DD; d++) acc += s_w[d * GG + g] * s_h[d];
        s_gh[g] = acc;
        __syncthreads();
        if (g < DD) {
            const float* xg = &g_vxg[((key * 16 + b) * 16 + t) * GG];
            float r = sigf(xg[g] + s_gh[g]);
            float z = sigf(xg[DD + g] + s_gh[DD + g]);
            float nn = tanhf(xg[2 * DD + g] + r * s_gh[2 * DD + g]);
            s_h[g] = (1.f - z) * nn + z * s_h[g];
        }
        __syncthreads();
    }
    if (g < DD) g_hv[(key * 16 + b) * DD + g] = s_h[g];
}

// ---------------- K7: ReLU + final FC ------------------------------------------
__global__ void k_fc(const float* fcw, const float* fcb, float* out) {
    __shared__ float pe[7 * DD];
    int b = blockIdx.x, o = threadIdx.x;
    for (int i = o; i < 7 * DD; i += 256) {
        int k = i / DD, d = i % DD;
        pe[i] = fmaxf(g_hv[(k * 16 + b) * DD + d], 0.f);
    }
    __syncthreads();
    if (o < NOUT) {
        float acc = fcb[o];
        for (int j = 0; j < 7 * DD; j++) acc += pe[j] * fcw[j * NOUT + o];
        out[b * NOUT + o] = acc;
    }
}

// ---------------- launch ---------------------------------------------------------
extern "C" void kernel_launch(void* const* d_in, const int* in_sizes, int n_in,
                              void* d_out, int out_size) {
    const int* tok_cond      = (const int*)d_in[0];
    const int* tok_proc      = (const int*)d_in[1];
    const int* tok_drug      = (const int*)d_in[2];
    const int* tok_lab_item  = (const int*)d_in[3];
    const int* tok_lab_value = (const int*)d_in[4];
    const int* tok_inj_item  = (const int*)d_in[5];
    const int* tok_inj_value = (const int*)d_in[6];
    const float* weight      = (const float*)d_in[7];
    const float* age         = (const float*)d_in[8];
    const float* emb_cond    = (const float*)d_in[9];
    const float* emb_proc    = (const float*)d_in[10];
    const float* emb_drug    = (const float*)d_in[11];
    const float* emb_li      = (const float*)d_in[12];
    const float* emb_lv      = (const float*)d_in[13];
    const float* emb_ii      = (const float*)d_in[14];
    const float* emb_iv      = (const float*)d_in[15];
    const float* mgru_wih    = (const float*)d_in[16];
    const float* mgru_whh    = (const float*)d_in[17];
    const float* mgru_bih    = (const float*)d_in[18];
    const float* mgru_bhh    = (const float*)d_in[19];
    const float* vgru_wih    = (const float*)d_in[20];
    const float* vgru_whh    = (const float*)d_in[21];
    const float* vgru_bih    = (const float*)d_in[22];
    const float* vgru_bhh    = (const float*)d_in[23];
    const float* info_w      = (const float*)d_in[24];
    const float* info_b      = (const float*)d_in[25];
    const float* fc_w        = (const float*)d_in[26];
    const float* fc_b        = (const float*)d_in[27];
    float* out = (float*)d_out;

    cudaFuncSetAttribute(k_mon_gru, cudaFuncAttributeMaxDynamicSharedMemorySize, 215040);
    cudaFuncSetAttribute(k_vis_gru, cudaFuncAttributeMaxDynamicSharedMemorySize, 198656);

    k_transpose<<<dim3(384, 24), 128>>>(mgru_wih, mgru_whh, vgru_wih, vgru_whh);
    k_embed_visit<<<dim3(256, 3), 128>>>(tok_cond, tok_proc, tok_drug,
                                         emb_cond, emb_proc, emb_drug);
    k_embed_mon<<<dim3(2048, 2), 128>>>(tok_lab_item, tok_lab_value,
                                        tok_inj_item, tok_inj_value,
                                        emb_li, emb_lv, emb_ii, emb_iv);
    k_xg34<<<dim3(256, 2), 384>>>(mgru_bih);
    k_xg012<<<dim3(256, 3), 384>>>(mgru_bih);
    k_mon_gru<<<dim3(29, 5), 384, 215040>>>(mgru_bhh);
    k_vxg<<<dim3(16, 7), 384>>>(weight, age, info_w, info_b, vgru_bih);
    k_vis_gru<<<dim3(16, 7), 384, 198656>>>(vgru_bhh);
    k_fc<<<16, 256>>>(fc_w, fc_b, out);
}